// round 1
// baseline (speedup 1.0000x reference)
#include <cuda_runtime.h>

#define NB   16
#define CIN  512
#define COUT 512
#define RES  64

// ---------------- device scratch (static, allowed) ----------------
__device__ float g_styles[NB * CIN];
__device__ float g_s[NB * CIN];
__device__ float g_rn[COUT];
__device__ float g_qraw[COUT * CIN];
__device__ float g_d[NB * COUT];
__device__ float g_wtm[CIN * 9 * COUT];          // [i*9+kk][oc]  (oc contiguous)
__device__ float g_xp[NB * CIN * 68 * 68];       // padded, style-scaled input
__device__ float g_y0[NB * COUT * 66 * 66];      // conv output (+d, +bias)

// ---------------- K1: styles = w @ aw^T / sqrt(512) + ab ----------------
__global__ void k_styles(const float* __restrict__ w,
                         const float* __restrict__ aw,
                         const float* __restrict__ ab) {
    int n = blockIdx.x;
    int tid = threadIdx.x;
    __shared__ float wsh[512];
    wsh[tid] = w[n * 512 + tid];
    __syncthreads();
    int warp = tid >> 5, lane = tid & 31;
    for (int i = warp; i < 512; i += 16) {
        float acc = 0.f;
        const float* row = aw + (size_t)i * 512;
        for (int j = lane; j < 512; j += 32) acc += wsh[j] * row[j];
        #pragma unroll
        for (int off = 16; off; off >>= 1) acc += __shfl_down_sync(0xffffffffu, acc, off);
        if (lane == 0)
            g_styles[n * 512 + i] = acc * 0.04419417382415922f + ab[i];
    }
}

// ---------------- K2: s = styles * rsqrt(mean(styles^2)) ----------------
__global__ void k_snorm() {
    int tid = threadIdx.x;                     // block 256, grid 1
    __shared__ float red[256];
    __shared__ float rstd_s;
    float a = 0.f;
    for (int idx = tid; idx < NB * CIN; idx += 256) {
        float v = g_styles[idx];
        a += v * v;
    }
    red[tid] = a;
    __syncthreads();
    for (int off = 128; off; off >>= 1) {
        if (tid < off) red[tid] += red[tid + off];
        __syncthreads();
    }
    if (tid == 0) rstd_s = rsqrtf(red[0] / (float)(NB * CIN));
    __syncthreads();
    float rs = rstd_s;
    for (int idx = tid; idx < NB * CIN; idx += 256)
        g_s[idx] = g_styles[idx] * rs;
}

// ---------------- K3: rn[o], qraw[o][i], wtm transposed ----------------
__global__ void k_rn(const float* __restrict__ cw) {
    int o = blockIdx.x;                        // grid 512, block 256
    int tid = threadIdx.x;
    const float* cwo = cw + (size_t)o * 4608;
    __shared__ float red[256];
    __shared__ float rn_s;
    float a = 0.f;
    for (int idx = tid; idx < 4608; idx += 256) {
        float v = cwo[idx];
        a += v * v;
    }
    red[tid] = a;
    __syncthreads();
    for (int off = 128; off; off >>= 1) {
        if (tid < off) red[tid] += red[tid + off];
        __syncthreads();
    }
    if (tid == 0) {
        rn_s = rsqrtf(red[0] / 4608.f);
        g_rn[o] = rn_s;
    }
    __syncthreads();
    float rn = rn_s;
    for (int i = tid; i < 512; i += 256) {
        float q = 0.f;
        #pragma unroll
        for (int kk = 0; kk < 9; kk++) {
            float v = cwo[i * 9 + kk];
            q += v * v;
        }
        g_qraw[o * 512 + i] = q;
    }
    for (int idx = tid; idx < 4608; idx += 256)
        g_wtm[(size_t)idx * 512 + o] = cwo[idx] * rn;
}

// ---------------- K4: d[n][o] ----------------
__global__ void k_d() {
    int n = blockIdx.x;                        // grid 16, block 512
    int tid = threadIdx.x;
    __shared__ float s2[512];
    float sv = g_s[n * 512 + tid];
    s2[tid] = sv * sv;
    __syncthreads();
    int warp = tid >> 5, lane = tid & 31;
    for (int o = warp; o < 512; o += 16) {
        float acc = 0.f;
        const float* qr = g_qraw + (size_t)o * 512;
        for (int i = lane; i < 512; i += 32) acc += s2[i] * qr[i];
        #pragma unroll
        for (int off = 16; off; off >>= 1) acc += __shfl_down_sync(0xffffffffu, acc, off);
        if (lane == 0) {
            float rn = g_rn[o];
            g_d[n * 512 + o] = rsqrtf(rn * rn * acc + 1e-8f);
        }
    }
}

// ---------------- K5: padded, scaled input ----------------
__global__ void k_pad(const float* __restrict__ x) {
    int i = blockIdx.x;                        // grid (512,16), block 256
    int n = blockIdx.y;
    int tid = threadIdx.x;
    float s = g_s[n * 512 + i];
    const float* in = x + ((size_t)(n * 512 + i)) * (RES * RES);
    float* out = g_xp + ((size_t)(n * 512 + i)) * (68 * 68);
    for (int idx = tid; idx < 68 * 68; idx += 256) {
        int yy = idx / 68, xx = idx % 68;
        float v = 0.f;
        if (yy >= 2 && yy < 66 && xx >= 2 && xx < 66)
            v = in[(yy - 2) * 64 + (xx - 2)] * s;
        out[idx] = v;
    }
}

// ---------------- K6: conv (implicit GEMM, FFMA) ----------------
// CTA: 128 out-ch x (2 rows x 72 cols, 66 real). block 256 = 16(px) x 16(oc).
__global__ __launch_bounds__(256, 2) void k_conv(const float* __restrict__ cbias) {
    __shared__ float xs[8 * 4 * 76];           // [c][row 4][col 76]
    __shared__ float ws[8 * 9 * 128];          // [c][kk][oc 128]

    int t   = blockIdx.x;                      // 0..32  row pair
    int ocb = blockIdx.y;                      // 0..3
    int n   = blockIdx.z;                      // 0..15
    int tid = threadIdx.x;
    int tx  = tid & 15, ty = tid >> 4;
    int r   = tx >> 3;                         // row within pair
    int cc0 = (tx & 7) * 9;                    // col base (0..63 step 9)

    float acc[8][9];
    #pragma unroll
    for (int m = 0; m < 8; m++)
        #pragma unroll
        for (int j = 0; j < 9; j++) acc[m][j] = 0.f;

    const float4* wtm4 = reinterpret_cast<const float4*>(g_wtm);

    for (int cb = 0; cb < 512; cb += 8) {
        __syncthreads();
        // input patch: rows 2t .. 2t+3, cols 0..75 (>=68 zero)
        for (int idx = tid; idx < 8 * 4 * 76; idx += 256) {
            int c = idx / 304;
            int rem = idx - c * 304;
            int rr = rem / 76;
            int col = rem - rr * 76;
            int row = 2 * t + rr;
            float v = 0.f;
            if (col < 68)
                v = g_xp[(((size_t)(n * 512 + cb + c)) * 68 + row) * 68 + col];
            xs[idx] = v;
        }
        // weights: [c][kk][128 oc] as float4
        float4* ws4 = reinterpret_cast<float4*>(ws);
        for (int idx = tid; idx < 8 * 9 * 32; idx += 256) {
            int rowidx = idx >> 5;             // c*9 + kk
            int j = idx & 31;
            ws4[idx] = wtm4[((size_t)(cb * 9 + rowidx)) * 128 + ocb * 32 + j];
        }
        __syncthreads();

        for (int c = 0; c < 8; c++) {
            #pragma unroll
            for (int ky = 0; ky < 3; ky++) {
                float xr[11];
                const float* xrow = &xs[c * 304 + (r + ky) * 76 + cc0];
                #pragma unroll
                for (int j = 0; j < 11; j++) xr[j] = xrow[j];
                #pragma unroll
                for (int kx = 0; kx < 3; kx++) {
                    const float* wp = &ws[(c * 9 + ky * 3 + kx) * 128 + ty * 8];
                    float wv[8];
                    #pragma unroll
                    for (int m = 0; m < 8; m++) wv[m] = wp[m];
                    #pragma unroll
                    for (int m = 0; m < 8; m++)
                        #pragma unroll
                        for (int j = 0; j < 9; j++)
                            acc[m][j] = fmaf(wv[m], xr[kx + j], acc[m][j]);
                }
            }
        }
    }

    // epilogue: * d[n][oc] + bias
    int oy = 2 * t + r;
    #pragma unroll
    for (int m = 0; m < 8; m++) {
        int oc = ocb * 128 + ty * 8 + m;
        float dd = g_d[n * 512 + oc];
        float bb = cbias[oc];
        float* dst = g_y0 + (((size_t)(n * 512 + oc)) * 66 + oy) * 66;
        #pragma unroll
        for (int j = 0; j < 9; j++) {
            int cc = cc0 + j;
            if (cc < 66) dst[cc] = acc[m][j] * dd + bb;
        }
    }
}

// ---------------- K7: fused filtered_lrelu ----------------
// one CTA per (n,c) image. dynamic smem: A(19320) + B(10488) floats = 119232 B
__global__ __launch_bounds__(512) void k_flrelu(const float* __restrict__ uf,
                                                const float* __restrict__ dfl,
                                                float* __restrict__ out) {
    extern __shared__ float sm[];
    float* A = sm;                 // SIN [76][68] then Z [138][140]
    float* B = sm + 19320;         // T1 [138][76] then V [138][64]
    __shared__ float fs[12], ds[12];

    int tid = threadIdx.x;
    if (tid < 12) fs[tid] = uf[tid];
    else if (tid < 24) ds[tid - 12] = dfl[tid - 12];

    const float* img = g_y0 + (size_t)blockIdx.x * (66 * 66);

    // P0: SIN (rows 5..70 hold data, rest zero)
    for (int idx = tid; idx < 76 * 68; idx += 512) {
        int row = idx / 68, col = idx % 68;
        int ry = row - 5;
        float v = 0.f;
        if (ry >= 0 && ry < 66 && col < 66) v = img[ry * 66 + col];
        A[idx] = v;
    }
    __syncthreads();

    // P1: vertical up-FIR -> T1[138][76] (cols 5..70 data)
    for (int idx = tid; idx < 138 * 76; idx += 512) {
        int uy = idx / 76, cc2 = idx - uy * 76;
        float acc = 0.f;
        if (cc2 >= 5 && cc2 < 71) {
            int x = cc2 - 5;
            int t0 = (9 - uy) & 1;
            int q0 = (uy + t0 - 9) >> 1;
            #pragma unroll
            for (int k = 0; k < 6; k++)
                acc += fs[t0 + 2 * k] * A[(q0 + k + 5) * 68 + x];
        }
        B[idx] = acc;
    }
    __syncthreads();

    // P2: horizontal up-FIR, gain 4, lrelu*sqrt2, clamp -> Z in A [138][140]
    for (int idx = tid; idx < 138 * 138; idx += 512) {
        int uy = idx / 138, ux = idx - uy * 138;
        int t0 = (9 - ux) & 1;
        int q0 = (ux + t0 - 9) >> 1;
        float acc = 0.f;
        #pragma unroll
        for (int k = 0; k < 6; k++)
            acc += fs[t0 + 2 * k] * B[uy * 76 + (q0 + k + 5)];
        float y4 = 4.f * acc;
        float l = (y4 >= 0.f ? y4 : 0.2f * y4) * 1.4142135623730951f;
        l = fminf(fmaxf(l, -256.f), 256.f);
        A[uy * 140 + ux] = l;
    }
    __syncthreads();

    // P3: horizontal down-FIR -> V in B [138][64]
    for (int idx = tid; idx < 138 * 64; idx += 512) {
        int uy = idx / 64, ox = idx - uy * 64;
        float acc = 0.f;
        #pragma unroll
        for (int tt = 0; tt < 12; tt++)
            acc += ds[tt] * A[uy * 140 + 2 * ox + tt];
        B[uy * 64 + ox] = acc;
    }
    __syncthreads();

    // P4: vertical down-FIR -> out
    float* o = out + (size_t)blockIdx.x * (64 * 64);
    for (int idx = tid; idx < 64 * 64; idx += 512) {
        int oy = idx >> 6, ox = idx & 63;
        float acc = 0.f;
        #pragma unroll
        for (int i = 0; i < 12; i++)
            acc += ds[i] * B[(2 * oy + i) * 64 + ox];
        o[idx] = acc;
    }
}

// ---------------- launch ----------------
extern "C" void kernel_launch(void* const* d_in, const int* in_sizes, int n_in,
                              void* d_out, int out_size) {
    const float* x  = (const float*)d_in[0];
    const float* w  = (const float*)d_in[1];
    const float* aw = (const float*)d_in[2];
    const float* ab = (const float*)d_in[3];
    const float* cw = (const float*)d_in[4];
    const float* cb = (const float*)d_in[5];
    const float* uf = (const float*)d_in[6];
    const float* df = (const float*)d_in[7];
    float* out = (float*)d_out;

    (void)in_sizes; (void)n_in; (void)out_size;

    cudaFuncSetAttribute(k_flrelu, cudaFuncAttributeMaxDynamicSharedMemorySize, 119232);

    k_styles<<<NB, 512>>>(w, aw, ab);
    k_snorm<<<1, 256>>>();
    k_rn<<<COUT, 256>>>(cw);
    k_d<<<NB, 512>>>();
    k_pad<<<dim3(CIN, NB), 256>>>(x);
    k_conv<<<dim3(33, 4, NB), 256>>>(cb);
    k_flrelu<<<NB * COUT, 512, 119232>>>(uf, df, out);
}

// round 3
// speedup vs baseline: 4.3445x; 4.3445x over previous
#include <cuda_runtime.h>
#include <cuda_fp16.h>
#include <cstdint>

#define NB   16
#define CIN  512
#define COUT 512
#define RES  64

// ---------------- device scratch ----------------
__device__ float  g_styles[NB * CIN];
__device__ float  g_s[NB * CIN];
__device__ float  g_rn[COUT];
__device__ float  g_qraw[COUT * CIN];
__device__ float  g_d[NB * COUT];
__device__ __half g_wth[9 * COUT * CIN];            // [kk][oc][i] fp16
__device__ __half g_xph[NB * 68 * 68 * CIN];        // NHWC padded, style-scaled fp16
__device__ float  g_y0[NB * COUT * 66 * 66];        // conv out (+d, +bias) fp32

// ---------------- helpers ----------------
__device__ __forceinline__ uint32_t smem_u32(const void* p) {
    uint32_t a;
    asm("{ .reg .u64 t; cvta.to.shared.u64 t, %1; cvt.u32.u64 %0, t; }" : "=r"(a) : "l"(p));
    return a;
}
__device__ __forceinline__ uint32_t swz(uint32_t o) { return o ^ ((o >> 3) & 0x70); }

__device__ __forceinline__ void ldsm4(uint32_t* r, uint32_t addr) {
    asm volatile("ldmatrix.sync.aligned.m8n8.x4.shared.b16 {%0,%1,%2,%3}, [%4];"
        : "=r"(r[0]), "=r"(r[1]), "=r"(r[2]), "=r"(r[3]) : "r"(addr));
}
__device__ __forceinline__ void mma16816(float* c, const uint32_t* a, uint32_t b0, uint32_t b1) {
    asm volatile("mma.sync.aligned.m16n8k16.row.col.f32.f16.f16.f32 "
        "{%0,%1,%2,%3}, {%4,%5,%6,%7}, {%8,%9}, {%0,%1,%2,%3};"
        : "+f"(c[0]), "+f"(c[1]), "+f"(c[2]), "+f"(c[3])
        : "r"(a[0]), "r"(a[1]), "r"(a[2]), "r"(a[3]), "r"(b0), "r"(b1));
}

// ---------------- K1: styles ----------------
__global__ void k_styles(const float* __restrict__ w,
                         const float* __restrict__ aw,
                         const float* __restrict__ ab) {
    int n = blockIdx.x, tid = threadIdx.x;
    __shared__ float wsh[512];
    wsh[tid] = w[n * 512 + tid];
    __syncthreads();
    int warp = tid >> 5, lane = tid & 31;
    for (int i = warp; i < 512; i += 16) {
        float acc = 0.f;
        const float* row = aw + (size_t)i * 512;
        for (int j = lane; j < 512; j += 32) acc += wsh[j] * row[j];
        #pragma unroll
        for (int off = 16; off; off >>= 1) acc += __shfl_down_sync(0xffffffffu, acc, off);
        if (lane == 0) g_styles[n * 512 + i] = acc * 0.04419417382415922f + ab[i];
    }
}

// ---------------- K2: s normalize ----------------
__global__ void k_snorm() {
    int tid = threadIdx.x;
    __shared__ float red[256];
    __shared__ float rstd_s;
    float a = 0.f;
    for (int idx = tid; idx < NB * CIN; idx += 256) { float v = g_styles[idx]; a += v * v; }
    red[tid] = a; __syncthreads();
    for (int off = 128; off; off >>= 1) { if (tid < off) red[tid] += red[tid + off]; __syncthreads(); }
    if (tid == 0) rstd_s = rsqrtf(red[0] / (float)(NB * CIN));
    __syncthreads();
    float rs = rstd_s;
    for (int idx = tid; idx < NB * CIN; idx += 256) g_s[idx] = g_styles[idx] * rs;
}

// ---------------- K3: rn, qraw, wth[kk][oc][i] fp16 ----------------
__global__ void k_rn(const float* __restrict__ cw) {
    int o = blockIdx.x, tid = threadIdx.x;
    const float* cwo = cw + (size_t)o * 4608;
    __shared__ float red[256];
    __shared__ float rn_s;
    float a = 0.f;
    for (int idx = tid; idx < 4608; idx += 256) { float v = cwo[idx]; a += v * v; }
    red[tid] = a; __syncthreads();
    for (int off = 128; off; off >>= 1) { if (tid < off) red[tid] += red[tid + off]; __syncthreads(); }
    if (tid == 0) { rn_s = rsqrtf(red[0] / 4608.f); g_rn[o] = rn_s; }
    __syncthreads();
    float rn = rn_s;
    for (int i = tid; i < 512; i += 256) {
        float q = 0.f;
        #pragma unroll
        for (int kk = 0; kk < 9; kk++) { float v = cwo[i * 9 + kk]; q += v * v; }
        g_qraw[o * 512 + i] = q;
    }
    #pragma unroll
    for (int kk = 0; kk < 9; kk++)
        for (int i = tid; i < 512; i += 256)
            g_wth[((size_t)(kk * 512) + o) * 512 + i] = __float2half(cwo[i * 9 + kk] * rn);
}

// ---------------- K4: d[n][o] ----------------
__global__ void k_d() {
    int n = blockIdx.x, tid = threadIdx.x;
    __shared__ float s2[512];
    float sv = g_s[n * 512 + tid];
    s2[tid] = sv * sv;
    __syncthreads();
    int warp = tid >> 5, lane = tid & 31;
    for (int o = warp; o < 512; o += 16) {
        float acc = 0.f;
        const float* qr = g_qraw + (size_t)o * 512;
        for (int i = lane; i < 512; i += 32) acc += s2[i] * qr[i];
        #pragma unroll
        for (int off = 16; off; off >>= 1) acc += __shfl_down_sync(0xffffffffu, acc, off);
        if (lane == 0) { float rn = g_rn[o]; g_d[n * 512 + o] = rsqrtf(rn * rn * acc + 1e-8f); }
    }
}

// ---------------- K5: NHWC padded, scaled input fp16 ----------------
__global__ __launch_bounds__(512) void k_pad(const float* __restrict__ x) {
    int yy = blockIdx.x, n = blockIdx.y, tid = threadIdx.x;
    __shared__ float ts[128][65];
    __half* orow = g_xph + ((size_t)(n * 68 + yy) * 68) * 512;
    bool inner = (yy >= 2 && yy < 66);
    for (int ct = 0; ct < 4; ct++) {
        __syncthreads();
        if (inner) {
            #pragma unroll
            for (int it = 0; it < 16; it++) {
                int idx = it * 512 + tid;
                int c = idx >> 6, xx = idx & 63;
                int cg = ct * 128 + c;
                ts[c][xx] = x[(((size_t)(n * 512) + cg) * 64 + (yy - 2)) * 64 + xx] * g_s[n * 512 + cg];
            }
        }
        __syncthreads();
        #pragma unroll
        for (int it = 0; it < 17; it++) {
            int idx = it * 512 + tid;
            if (idx < 68 * 128) {
                int xx = idx >> 7, c = idx & 127;
                float v = 0.f;
                if (inner && xx >= 2 && xx < 66) v = ts[c][xx - 2];
                orow[xx * 512 + ct * 128 + c] = __float2half(v);
            }
        }
    }
}

// ---------------- K6: conv via mma.sync fp16 implicit GEMM ----------------
// grid (18 ptile, 4 octile, 16 n), 256 threads. CTA tile 128 oc x 256 px.
// K = 4608 = 72 steps of 64 halves. 3-stage cp.async pipeline.
#define STAGE_B 49152
__global__ __launch_bounds__(256, 1) void k_conv(const float* __restrict__ cbias) {
    extern __shared__ char smem[];
    uint32_t sb = smem_u32(smem);
    int tid = threadIdx.x, lane = tid & 31, wid = tid >> 5;
    int pt = blockIdx.x, ot = blockIdx.y, n = blockIdx.z;
    int p0 = pt * 256;
    int wm = wid & 1, wn = wid >> 1;

    float C[4][8][4];
    #pragma unroll
    for (int i = 0; i < 4; i++)
        #pragma unroll
        for (int j = 0; j < 8; j++)
            #pragma unroll
            for (int k = 0; k < 4; k++) C[i][j][k] = 0.f;

    int ch = tid & 7;
    int trow = tid >> 3;

    // B pixel row base offsets (half-element units)
    uint32_t browoff[8];
    #pragma unroll
    for (int b = 0; b < 8; b++) {
        int row = b * 32 + trow;
        int p = p0 + row; if (p > 4355) p = 4355;
        int y = p / 66, xx = p - y * 66;
        browoff[b] = ((uint32_t)(n * 68 + y) * 68 + xx) * 512;
    }
    // smem store offsets (within stage)
    uint32_t sA_st[4], sB_st[8];
    #pragma unroll
    for (int a = 0; a < 4; a++) sA_st[a] = swz(((a * 32 + trow) * 128) + ch * 16);
    #pragma unroll
    for (int b = 0; b < 8; b++) sB_st[b] = 16384 + swz(((b * 32 + trow) * 128) + ch * 16);

#define LOAD_TILE(js_, slot_) do { \
    int kk_ = (js_) >> 3; int i0_ = ((js_) & 7) << 6; \
    int ky_ = kk_ / 3, kx_ = kk_ - ky_ * 3; \
    uint32_t stb_ = sb + (uint32_t)(slot_) * STAGE_B; \
    const __half* ap_ = g_wth + ((size_t)(kk_ * 512 + ot * 128)) * 512 + i0_ + ch * 8; \
    _Pragma("unroll") \
    for (int a_ = 0; a_ < 4; a_++) { \
        uint32_t sa_ = stb_ + sA_st[a_]; \
        const __half* ga_ = ap_ + (size_t)(a_ * 32 + trow) * 512; \
        asm volatile("cp.async.cg.shared.global [%0], [%1], 16;" :: "r"(sa_), "l"(ga_)); \
    } \
    uint32_t koff_ = (uint32_t)(ky_ * 68 + kx_) * 512 + i0_ + ch * 8; \
    _Pragma("unroll") \
    for (int b_ = 0; b_ < 8; b_++) { \
        uint32_t sa_ = stb_ + sB_st[b_]; \
        const __half* gb_ = g_xph + browoff[b_] + koff_; \
        asm volatile("cp.async.cg.shared.global [%0], [%1], 16;" :: "r"(sa_), "l"(gb_)); \
    } \
    asm volatile("cp.async.commit_group;" ::: "memory"); \
} while (0)

    LOAD_TILE(0, 0);
    LOAD_TILE(1, 1);

    // ldmatrix per-lane address components
    uint32_t aRow = wm * 64 + (lane & 15);
    uint32_t aCol = (uint32_t)(lane >> 4);
    uint32_t bRow = wn * 64 + ((lane >> 4) << 3) + (lane & 7);
    uint32_t bCol = (uint32_t)((lane >> 3) & 1);

    for (int js = 0; js < 72; js++) {
        int cur = js % 3;
        asm volatile("cp.async.wait_group 1;" ::: "memory");
        __syncthreads();
        if (js + 2 < 72) { LOAD_TILE(js + 2, (js + 2) % 3); }
        else { asm volatile("cp.async.commit_group;" ::: "memory"); }

        uint32_t sA = sb + (uint32_t)cur * STAGE_B;
        uint32_t sB = sA + 16384;
        #pragma unroll
        for (int ks = 0; ks < 4; ks++) {
            uint32_t af[4][4], bf[4][4];
            #pragma unroll
            for (int mt = 0; mt < 4; mt++)
                ldsm4(af[mt], sA + swz((aRow + mt * 16) * 128 + (ks * 2 + aCol) * 16));
            #pragma unroll
            for (int bt = 0; bt < 4; bt++)
                ldsm4(bf[bt], sB + swz((bRow + bt * 16) * 128 + (ks * 2 + bCol) * 16));
            #pragma unroll
            for (int mt = 0; mt < 4; mt++)
                #pragma unroll
                for (int bt = 0; bt < 4; bt++) {
                    mma16816(C[mt][2 * bt],     af[mt], bf[bt][0], bf[bt][1]);
                    mma16816(C[mt][2 * bt + 1], af[mt], bf[bt][2], bf[bt][3]);
                }
        }
    }

    // ---- epilogue: *d + bias -> g_y0 ----
    int obase = ot * 128 + wm * 64;
    float* y0n = g_y0 + (size_t)n * 512 * 4356;
    #pragma unroll
    for (int mt = 0; mt < 4; mt++) {
        int r0 = obase + mt * 16 + (lane >> 2);
        int r1 = r0 + 8;
        float d0 = g_d[n * 512 + r0], bb0 = cbias[r0];
        float d1 = g_d[n * 512 + r1], bb1 = cbias[r1];
        float* row0 = y0n + (size_t)r0 * 4356;
        float* row1 = y0n + (size_t)r1 * 4356;
        #pragma unroll
        for (int nt = 0; nt < 8; nt++) {
            int p = p0 + wn * 64 + nt * 8 + 2 * (lane & 3);
            if (p + 1 < 4356) {
                *(float2*)(row0 + p) = make_float2(C[mt][nt][0] * d0 + bb0, C[mt][nt][1] * d0 + bb0);
                *(float2*)(row1 + p) = make_float2(C[mt][nt][2] * d1 + bb1, C[mt][nt][3] * d1 + bb1);
            } else if (p < 4356) {
                row0[p] = C[mt][nt][0] * d0 + bb0;
                row1[p] = C[mt][nt][2] * d1 + bb1;
            }
        }
    }
}

// ---------------- K7: fused filtered_lrelu ----------------
__global__ __launch_bounds__(512) void k_flrelu(const float* __restrict__ uf,
                                                const float* __restrict__ dfl,
                                                float* __restrict__ out) {
    extern __shared__ float sm[];
    float* A = sm;                 // SIN [76][68] then Z [138][140]
    float* B = sm + 19320;         // T1 [138][76] then V [138][64]
    __shared__ float fs[12], ds[12];

    int tid = threadIdx.x;
    if (tid < 12) fs[tid] = uf[tid];
    else if (tid < 24) ds[tid - 12] = dfl[tid - 12];

    const float* img = g_y0 + (size_t)blockIdx.x * (66 * 66);

    for (int idx = tid; idx < 76 * 68; idx += 512) {
        int row = idx / 68, col = idx % 68;
        int ry = row - 5;
        float v = 0.f;
        if (ry >= 0 && ry < 66 && col < 66) v = img[ry * 66 + col];
        A[idx] = v;
    }
    __syncthreads();

    for (int idx = tid; idx < 138 * 76; idx += 512) {
        int uy = idx / 76, cc2 = idx - uy * 76;
        float acc = 0.f;
        if (cc2 >= 5 && cc2 < 71) {
            int x = cc2 - 5;
            int t0 = (9 - uy) & 1;
            int q0 = (uy + t0 - 9) >> 1;
            #pragma unroll
            for (int k = 0; k < 6; k++)
                acc += fs[t0 + 2 * k] * A[(q0 + k + 5) * 68 + x];
        }
        B[idx] = acc;
    }
    __syncthreads();

    for (int idx = tid; idx < 138 * 138; idx += 512) {
        int uy = idx / 138, ux = idx - uy * 138;
        int t0 = (9 - ux) & 1;
        int q0 = (ux + t0 - 9) >> 1;
        float acc = 0.f;
        #pragma unroll
        for (int k = 0; k < 6; k++)
            acc += fs[t0 + 2 * k] * B[uy * 76 + (q0 + k + 5)];
        float y4 = 4.f * acc;
        float l = (y4 >= 0.f ? y4 : 0.2f * y4) * 1.4142135623730951f;
        l = fminf(fmaxf(l, -256.f), 256.f);
        A[uy * 140 + ux] = l;
    }
    __syncthreads();

    for (int idx = tid; idx < 138 * 64; idx += 512) {
        int uy = idx / 64, ox = idx - uy * 64;
        float acc = 0.f;
        #pragma unroll
        for (int tt = 0; tt < 12; tt++)
            acc += ds[tt] * A[uy * 140 + 2 * ox + tt];
        B[uy * 64 + ox] = acc;
    }
    __syncthreads();

    float* o = out + (size_t)blockIdx.x * (64 * 64);
    for (int idx = tid; idx < 64 * 64; idx += 512) {
        int oy = idx >> 6, ox = idx & 63;
        float acc = 0.f;
        #pragma unroll
        for (int i = 0; i < 12; i++)
            acc += ds[i] * B[(2 * oy + i) * 64 + ox];
        o[idx] = acc;
    }
}

// ---------------- launch ----------------
extern "C" void kernel_launch(void* const* d_in, const int* in_sizes, int n_in,
                              void* d_out, int out_size) {
    const float* x  = (const float*)d_in[0];
    const float* w  = (const float*)d_in[1];
    const float* aw = (const float*)d_in[2];
    const float* ab = (const float*)d_in[3];
    const float* cw = (const float*)d_in[4];
    const float* cb = (const float*)d_in[5];
    const float* uf = (const float*)d_in[6];
    const float* df = (const float*)d_in[7];
    float* out = (float*)d_out;
    (void)in_sizes; (void)n_in; (void)out_size;

    cudaFuncSetAttribute(k_conv,   cudaFuncAttributeMaxDynamicSharedMemorySize, 3 * STAGE_B);
    cudaFuncSetAttribute(k_flrelu, cudaFuncAttributeMaxDynamicSharedMemorySize, 119232);

    k_styles<<<NB, 512>>>(w, aw, ab);
    k_snorm<<<1, 256>>>();
    k_rn<<<COUT, 256>>>(cw);
    k_d<<<NB, 512>>>();
    k_pad<<<dim3(68, NB), 512>>>(x);
    k_conv<<<dim3(18, 4, NB), 256, 3 * STAGE_B>>>(cb);
    k_flrelu<<<NB * COUT, 512, 119232>>>(uf, df, out);
}